// round 1
// baseline (speedup 1.0000x reference)
#include <cuda_runtime.h>
#include <math.h>

// Problem constants: B=4, C=2, H=W=1024, DS=4 -> Hd=Wd=256, NUM_SEEDS=32, 15 steps.
#define NCH   128          // B * NUM_SEEDS channels
#define RS    97           // region size: seed +/- 48
#define PITCH 104          // smem row pitch (floats)
#define SMEM_BYTES (3 * RS * PITCH * 4)

__device__ float g_road[4 * 256 * 256];     // pred mask (bilinear-downsampled road prob)
__device__ float g_gt[4 * 256 * 256];       // gt mask (strided label sample)
__device__ int   g_sr[NCH];
__device__ int   g_sc[NCH];
__device__ int   g_scnt[NCH];
__device__ float g_sv[NCH];
__device__ float g_partial[NCH];

__global__ void k_init() {
    int t = threadIdx.x;
    if (t < NCH) { g_scnt[t] = 0; g_partial[t] = 0.f; }
}

// Find the (single) seed pixel per channel.
__global__ void k_seed_scan(const float4* __restrict__ seeds) {
    const int n4 = (4 * 32 * 256 * 256) / 4;
    for (int i = blockIdx.x * blockDim.x + threadIdx.x; i < n4; i += gridDim.x * blockDim.x) {
        float4 v = seeds[i];
        if (v.x > 0.f || v.y > 0.f || v.z > 0.f || v.w > 0.f) {
            float vals[4] = {v.x, v.y, v.z, v.w};
            #pragma unroll
            for (int k = 0; k < 4; k++) if (vals[k] > 0.f) {
                int idx = i * 4 + k;
                int ch = idx >> 16;
                int r  = (idx >> 8) & 255;
                int c  = idx & 255;
                if (atomicAdd(&g_scnt[ch], 1) == 0) {
                    g_sr[ch] = r; g_sc[ch] = c; g_sv[ch] = vals[k];
                }
            }
        }
    }
}

// road_ds[b,i,j] = 0.25 * sum sigmoid(x1-x0) over rows {4i+1,4i+2} x cols {4j+1,4j+2}
// gt_ds[b,i,j]   = (float) label[b, 4i, 4j]
__global__ void k_masks(const float* __restrict__ cls, const int* __restrict__ lab) {
    int idx = blockIdx.x * blockDim.x + threadIdx.x;
    if (idx >= 4 * 256 * 256) return;
    int j = idx & 255, i = (idx >> 8) & 255, b = idx >> 16;
    const float* c0 = cls + (size_t)(b * 2 + 0) * 1048576;
    const float* c1 = cls + (size_t)(b * 2 + 1) * 1048576;
    int r1 = 4 * i + 1, r2 = 4 * i + 2, cc = 4 * j;
    float4 a0 = *(const float4*)(c0 + r1 * 1024 + cc);
    float4 a1 = *(const float4*)(c1 + r1 * 1024 + cc);
    float4 b0 = *(const float4*)(c0 + r2 * 1024 + cc);
    float4 b1 = *(const float4*)(c1 + r2 * 1024 + cc);
    float p1 = 1.f / (1.f + expf(a0.y - a1.y));
    float p2 = 1.f / (1.f + expf(a0.z - a1.z));
    float p3 = 1.f / (1.f + expf(b0.y - b1.y));
    float p4 = 1.f / (1.f + expf(b0.z - b1.z));
    g_road[idx] = 0.25f * (p1 + p2 + p3 + p4);
    g_gt[idx]   = (float)lab[((size_t)b * 1024 + 4 * i) * 1024 + 4 * j];
}

// One CTA per (b,c) channel. Runs the full 15-step reconstruction for gt then pred
// entirely in shared memory over the 97x97 active region, then fuses the BCE sum.
__global__ void __launch_bounds__(512, 1) k_flood() {
    extern __shared__ float sm[];
    float* A  = sm;                    // state
    float* Bt = sm + RS * PITCH;       // horizontal-pass temp
    float* M  = sm + 2 * RS * PITCH;   // mask crop
    __shared__ unsigned int G[RS * 4]; // gt result bitmask
    __shared__ float wpart[16];

    int ch  = blockIdx.x;
    int tid = threadIdx.x;
    int b   = ch >> 5;
    const float c0log = -logf(1.0f - 1e-7f);  // bce of (p=0, g=0) pixel

    int cnt = g_scnt[ch];
    if (cnt == 0) {                       // no seed: whole channel is the constant
        if (tid == 0) g_partial[ch] = 65536.0f * c0log;
        return;
    }
    int sr = g_sr[ch], sc = g_sc[ch];
    float sv = g_sv[ch];
    int gr0 = sr - 48, gc0 = sc - 48;

    float local = 0.f;

    for (int run = 0; run < 2; run++) {   // run 0: gt, run 1: pred
        const float* __restrict__ mask = run ? g_road : g_gt;

        // load mask crop (0 outside image), zero state
        for (int idx = tid; idx < RS * RS; idx += 512) {
            int y = idx / RS, x = idx - y * RS;
            int gy = gr0 + y, gx = gc0 + x;
            float m = 0.f;
            if ((unsigned)gy < 256u && (unsigned)gx < 256u)
                m = mask[(b << 16) + (gy << 8) + gx];
            M[y * PITCH + x] = m;
            A[y * PITCH + x] = 0.f;
        }
        __syncthreads();
        if (tid == 0) A[48 * PITCH + 48] = sv;   // s0 = seeds
        __syncthreads();

        for (int it = 0; it < 15; it++) {
            // --- horizontal 7-max: A -> Bt (4 outputs per unit, shared reads) ---
            for (int u = tid; u < RS * 25; u += 512) {
                int y = u / 25, xg = u - y * 25;
                const float* row = A + y * PITCH;
                int x0 = 4 * xg - 3;
                float r[10];
                #pragma unroll
                for (int k = 0; k < 10; k++) {
                    int xx = x0 + k;
                    xx = xx < 0 ? 0 : (xx > 96 ? 96 : xx);
                    r[k] = row[xx];
                }
                float p[9], q[7];
                #pragma unroll
                for (int k = 0; k < 9; k++) p[k] = fmaxf(r[k], r[k + 1]);
                #pragma unroll
                for (int k = 0; k < 7; k++) q[k] = fmaxf(p[k], p[k + 2]);
                float* orow = Bt + y * PITCH + 4 * xg;
                #pragma unroll
                for (int k = 0; k < 4; k++) orow[k] = fmaxf(q[k], q[k + 3]);
            }
            __syncthreads();
            // --- vertical 7-max + min(mask) + seed: Bt -> A (sliding window) ---
            if (tid < 485) {
                int colv = tid % 97;
                int band = tid / 97;
                int y0 = band * 20;
                float w[7];
                #pragma unroll
                for (int k = 0; k < 7; k++) {
                    int yy = y0 - 3 + k;
                    yy = yy < 0 ? 0 : yy;
                    w[k] = Bt[yy * PITCH + colv];
                }
                #pragma unroll
                for (int k = 0; k < 20; k++) {
                    int y = y0 + k;
                    if (y > 96) break;
                    float v = fmaxf(fmaxf(fmaxf(w[0], w[1]), fmaxf(w[2], w[3])),
                                    fmaxf(fmaxf(w[4], w[5]), w[6]));
                    v = fminf(M[y * PITCH + colv], v);
                    if (y == 48 && colv == 48) v = fmaxf(v, sv);
                    A[y * PITCH + colv] = v;
                    #pragma unroll
                    for (int q2 = 0; q2 < 6; q2++) w[q2] = w[q2 + 1];
                    int yn = y + 4;
                    w[6] = Bt[(yn > 96 ? 96 : yn) * PITCH + colv];
                }
            }
            __syncthreads();
        }

        if (run == 0) {
            // compress binary s_gt into bitmask
            for (int idx = tid; idx < RS * 4; idx += 512) {
                int y = idx >> 2, wd = idx & 3;
                unsigned bits = 0;
                int cb = wd * 32;
                #pragma unroll
                for (int k = 0; k < 32; k++) {
                    int c2 = cb + k;
                    if (c2 < 97 && A[y * PITCH + c2] > 0.5f) bits |= (1u << k);
                }
                G[idx] = bits;
            }
            __syncthreads();
        } else {
            // fused BCE over the +/-45 in-image box
            for (int idx = tid; idx < RS * RS; idx += 512) {
                int y = idx / RS, x = idx - y * RS;
                if (y < 3 || y > 93 || x < 3 || x > 93) continue;
                int gy = gr0 + y, gx = gc0 + x;
                if ((unsigned)gy >= 256u || (unsigned)gx >= 256u) continue;
                float pv = A[y * PITCH + x];
                pv = fminf(fmaxf(pv, 1e-7f), 1.0f - 1e-7f);
                unsigned gbit = (G[(y << 2) + (x >> 5)] >> (x & 31)) & 1u;
                local += gbit ? (-logf(pv)) : (-logf(1.0f - pv));
            }
        }
    }

    // block reduction -> deterministic per-channel slot
    #pragma unroll
    for (int off = 16; off; off >>= 1)
        local += __shfl_down_sync(0xffffffffu, local, off);
    if ((tid & 31) == 0) wpart[tid >> 5] = local;
    __syncthreads();
    if (tid == 0) {
        float s = 0.f;
        #pragma unroll
        for (int k = 0; k < 16; k++) s += wpart[k];
        int rlo = sr - 45 < 0 ? 0 : sr - 45;
        int rhi = sr + 45 > 255 ? 255 : sr + 45;
        int clo = sc - 45 < 0 ? 0 : sc - 45;
        int chi = sc + 45 > 255 ? 255 : sc + 45;
        float area = (float)((rhi - rlo + 1) * (chi - clo + 1));
        s += (65536.0f - area) * c0log;   // everything outside the box is (0,0)
        g_partial[ch] = s;
    }
}

__global__ void k_final(float* __restrict__ out) {
    float s = 0.f;
    for (int k = 0; k < NCH; k++) s += g_partial[k];   // fixed order: deterministic
    out[0] = 0.5f * s / 8388608.0f;
}

extern "C" void kernel_launch(void* const* d_in, const int* in_sizes, int n_in,
                              void* d_out, int out_size) {
    const float* cls = (const float*)d_in[0];
    const int* lab   = (const int*)d_in[1];
    const float4* seeds = (const float4*)d_in[2];

    cudaFuncSetAttribute(k_flood, cudaFuncAttributeMaxDynamicSharedMemorySize, SMEM_BYTES);

    k_init<<<1, 128>>>();
    k_seed_scan<<<1024, 256>>>(seeds);
    k_masks<<<1024, 256>>>(cls, lab);
    k_flood<<<128, 512, SMEM_BYTES>>>();
    k_final<<<1, 1>>>((float*)d_out);
}

// round 2
// speedup vs baseline: 1.8667x; 1.8667x over previous
#include <cuda_runtime.h>
#include <math.h>

// B=4, C=2, H=W=1024, DS=4 -> 256x256, NUM_SEEDS=32, 15 steps, pool 7x7.
#define NCH   128
#define RS    97           // active region: seed +/- 48
#define PITCH 104
#define SMEM_BYTES (3 * RS * PITCH * 4)

__device__ float    g_road[4 * 256 * 256];   // bilinear-downsampled road prob
__device__ unsigned g_gtb[4 * 256 * 8];      // gt label bits: [b][row][8 words], LSB = col 0 of word
__device__ int   g_sr[NCH];
__device__ int   g_sc[NCH];
__device__ int   g_scnt[NCH];
__device__ float g_sv[NCH];
__device__ float g_partial[NCH];

__global__ void k_init() {
    int t = threadIdx.x;
    if (t < NCH) g_scnt[t] = 0;
}

__global__ void k_seed_scan(const float4* __restrict__ seeds) {
    const int n4 = (4 * 32 * 256 * 256) / 4;
    for (int i = blockIdx.x * blockDim.x + threadIdx.x; i < n4; i += gridDim.x * blockDim.x) {
        float4 v = seeds[i];
        if (v.x > 0.f || v.y > 0.f || v.z > 0.f || v.w > 0.f) {
            float vals[4] = {v.x, v.y, v.z, v.w};
            #pragma unroll
            for (int k = 0; k < 4; k++) if (vals[k] > 0.f) {
                int idx = i * 4 + k;
                int ch = idx >> 16;
                if (atomicAdd(&g_scnt[ch], 1) == 0) {
                    g_sr[ch] = (idx >> 8) & 255;
                    g_sc[ch] = idx & 255;
                    g_sv[ch] = vals[k];
                }
            }
        }
    }
}

// road_ds[b,i,j] = 0.25 * sum sigmoid(x1-x0) over rows {4i+1,4i+2} x cols {4j+1,4j+2}
// gt bits: label[b, 4i, 4j] != 0
__global__ void k_masks(const float* __restrict__ cls, const int* __restrict__ lab) {
    int idx = blockIdx.x * blockDim.x + threadIdx.x;
    if (idx >= 4 * 256 * 256) return;
    int j = idx & 255, i = (idx >> 8) & 255, b = idx >> 16;
    const float* c0 = cls + (size_t)(b * 2 + 0) * 1048576;
    const float* c1 = cls + (size_t)(b * 2 + 1) * 1048576;
    int r1 = 4 * i + 1, r2 = 4 * i + 2, cc = 4 * j;
    float4 a0 = *(const float4*)(c0 + r1 * 1024 + cc);
    float4 a1 = *(const float4*)(c1 + r1 * 1024 + cc);
    float4 b0 = *(const float4*)(c0 + r2 * 1024 + cc);
    float4 b1 = *(const float4*)(c1 + r2 * 1024 + cc);
    float p1 = 1.f / (1.f + expf(a0.y - a1.y));
    float p2 = 1.f / (1.f + expf(a0.z - a1.z));
    float p3 = 1.f / (1.f + expf(b0.y - b1.y));
    float p4 = 1.f / (1.f + expf(b0.z - b1.z));
    g_road[idx] = 0.25f * (p1 + p2 + p3 + p4);
    int g = lab[((size_t)b * 1024 + 4 * i) * 1024 + 4 * j];
    unsigned bits = __ballot_sync(0xffffffffu, g != 0);
    if ((threadIdx.x & 31) == 0)
        g_gtb[((size_t)b * 256 + i) * 8 + (j >> 5)] = bits;
}

__device__ __forceinline__ unsigned getword(const unsigned* row, int start) {
    // bits [start, start+32) of a 256-bit row; out-of-range bits are 0
    int w = start >> 5;          // arithmetic shift: floor for negatives
    int sh = start & 31;
    unsigned lo = ((unsigned)w < 8u) ? row[w] : 0u;
    unsigned hi = ((unsigned)(w + 1) < 8u) ? row[w + 1] : 0u;
    return __funnelshift_r(lo, hi, sh);
}

__device__ __forceinline__ uint4 bshl(uint4 v, int s) {
    uint4 r;
    r.x = v.x << s;
    r.y = __funnelshift_l(v.x, v.y, s);
    r.z = __funnelshift_l(v.y, v.z, s);
    r.w = __funnelshift_l(v.z, v.w, s);
    return r;
}
__device__ __forceinline__ uint4 bshr(uint4 v, int s) {
    uint4 r;
    r.x = __funnelshift_r(v.x, v.y, s);
    r.y = __funnelshift_r(v.y, v.z, s);
    r.z = __funnelshift_r(v.z, v.w, s);
    r.w = v.w >> s;
    return r;
}
__device__ __forceinline__ uint4 bor(uint4 a, uint4 b) {
    return make_uint4(a.x | b.x, a.y | b.y, a.z | b.z, a.w | b.w);
}

// One CTA per channel: pred flood (float, growing window) + gt flood (bitwise)
// run concurrently in smem, then fused BCE.
__global__ void __launch_bounds__(512, 1) k_flood() {
    extern __shared__ float sm[];
    float* A  = sm;                    // pred state
    float* Bt = sm + RS * PITCH;       // horizontal-pass temp
    float* M  = sm + 2 * RS * PITCH;   // road mask crop
    __shared__ uint4 Gs[RS];           // gt state bits
    __shared__ uint4 Gh[RS];           // gt h-dilated bits
    __shared__ uint4 Gm[RS];           // gt mask bits
    __shared__ float wpart[16];

    int ch  = blockIdx.x;
    int tid = threadIdx.x;
    int b   = ch >> 5;
    const float c0log = -logf(1.0f - 1e-7f);

    if (g_scnt[ch] == 0) {
        if (tid == 0) g_partial[ch] = 65536.0f * c0log;
        return;
    }
    int sr = g_sr[ch], sc = g_sc[ch];
    float sv = g_sv[ch];
    int gr0 = sr - 48, gc0 = sc - 48;

    // ---- init: road crop, zero pred state, gt bits ----
    for (int idx = tid; idx < RS * RS; idx += 512) {
        int y = idx / RS, x = idx - y * RS;
        int gy = gr0 + y, gx = gc0 + x;
        float m = 0.f;
        if ((unsigned)gy < 256u && (unsigned)gx < 256u)
            m = g_road[(b << 16) + (gy << 8) + gx];
        M[y * PITCH + x] = m;
        A[y * PITCH + x] = 0.f;
    }
    if (tid < RS) {
        int gy = gr0 + tid;
        uint4 gm = make_uint4(0, 0, 0, 0);
        if ((unsigned)gy < 256u) {
            const unsigned* row = &g_gtb[((size_t)b * 256 + gy) * 8];
            gm.x = getword(row, gc0);
            gm.y = getword(row, gc0 + 32);
            gm.z = getword(row, gc0 + 64);
            gm.w = getword(row, gc0 + 96);
        }
        gm.w &= 1u;                 // kill window cols > 96
        Gm[tid] = gm;
        Gs[tid] = make_uint4(0, 0, 0, 0);
    }
    __syncthreads();
    if (tid == 0) {
        A[48 * PITCH + 48] = sv;                 // pred seed
        if (sv > 0.f) Gs[48].y |= (1u << 16);    // gt seed bit (col 48 = word 1, bit 16)
    }
    __syncthreads();

    for (int it = 0; it < 15; it++) {
        int R  = 3 * (it + 1);                   // <= 45: window never hits borders
        int lo = 48 - R, hi = 48 + R, W = 2 * R + 1;
        int rlo = lo - 3, nr = W + 6;
        int ng = (W + 3) >> 2;

        // --- float horizontal 7-max over rows [lo-3,hi+3] x cols [lo,hi] ---
        int total = nr * ng;
        for (int u = tid; u < total; u += 512) {
            int y = rlo + u / ng;
            int g = u - (u / ng) * ng;
            int xb = lo + 4 * g;
            const float* row = A + y * PITCH;
            float r[10];
            #pragma unroll
            for (int k = 0; k < 10; k++) {
                int xx = xb - 3 + k;
                xx = xx < 0 ? 0 : (xx > 96 ? 96 : xx);
                r[k] = row[xx];
            }
            float p[9], q[7];
            #pragma unroll
            for (int k = 0; k < 9; k++) p[k] = fmaxf(r[k], r[k + 1]);
            #pragma unroll
            for (int k = 0; k < 7; k++) q[k] = fmaxf(p[k], p[k + 2]);
            float* orow = Bt + y * PITCH + xb;
            #pragma unroll
            for (int k = 0; k < 4; k++) orow[k] = fmaxf(q[k], q[k + 3]);
        }
        // --- gt bitwise horizontal dilate (all 97 rows; cheap) ---
        if (tid < RS) {
            uint4 x = Gs[tid];
            uint4 d = bor(x, bor(bshl(x, 1), bshr(x, 1)));
            d = bor(d, bor(bshl(x, 2), bshr(x, 2)));
            d = bor(d, bor(bshl(x, 3), bshr(x, 3)));
            Gh[tid] = d;
        }
        __syncthreads();

        // --- float vertical 7-max + min(mask) + seed over [lo,hi]^2 ---
        int nb = 512 / W; if (nb > W) nb = W;
        int rpb = (W + nb - 1) / nb;
        if (tid < W * nb) {
            int colv = lo + tid % W;
            int band = tid / W;
            int y0 = lo + band * rpb;
            float w[7];
            #pragma unroll
            for (int k = 0; k < 7; k++) {
                int yy = y0 - 3 + k;
                w[k] = Bt[yy * PITCH + colv];
            }
            for (int k = 0; k < rpb; k++) {
                int y = y0 + k;
                if (y > hi) break;
                float v = fmaxf(fmaxf(fmaxf(w[0], w[1]), fmaxf(w[2], w[3])),
                                fmaxf(fmaxf(w[4], w[5]), w[6]));
                v = fminf(M[y * PITCH + colv], v);
                if (y == 48 && colv == 48) v = fmaxf(v, sv);
                A[y * PITCH + colv] = v;
                #pragma unroll
                for (int q2 = 0; q2 < 6; q2++) w[q2] = w[q2 + 1];
                int yn = y + 4; yn = yn > 96 ? 96 : yn;
                w[6] = Bt[yn * PITCH + colv];
            }
        }
        // --- gt bitwise vertical dilate + AND mask + seed ---
        if (tid < RS) {
            int y = tid;
            int ym3 = y - 3 < 0 ? 0 : y - 3;
            int yp3 = y + 3 > 96 ? 96 : y + 3;
            uint4 a = Gh[ym3];
            for (int yy = ym3 + 1; yy <= yp3; yy++) a = bor(a, Gh[yy]);
            a.x &= Gm[y].x; a.y &= Gm[y].y; a.z &= Gm[y].z; a.w &= Gm[y].w;
            if (y == 48 && sv > 0.f) a.y |= (1u << 16);
            Gs[y] = a;
        }
        __syncthreads();
    }

    // ---- fused BCE over the +/-45 in-image box ----
    float local = 0.f;
    for (int idx = tid; idx < RS * RS; idx += 512) {
        int y = idx / RS, x = idx - y * RS;
        if (y < 3 || y > 93 || x < 3 || x > 93) continue;
        int gy = gr0 + y, gx = gc0 + x;
        if ((unsigned)gy >= 256u || (unsigned)gx >= 256u) continue;
        float pv = A[y * PITCH + x];
        pv = fminf(fmaxf(pv, 1e-7f), 1.0f - 1e-7f);
        uint4 gw = Gs[y];
        int ws = x >> 5;
        unsigned word = ws == 0 ? gw.x : ws == 1 ? gw.y : ws == 2 ? gw.z : gw.w;
        unsigned gbit = (word >> (x & 31)) & 1u;
        local += gbit ? (-logf(pv)) : (-logf(1.0f - pv));
    }

    #pragma unroll
    for (int off = 16; off; off >>= 1)
        local += __shfl_down_sync(0xffffffffu, local, off);
    if ((tid & 31) == 0) wpart[tid >> 5] = local;
    __syncthreads();
    if (tid == 0) {
        float s = 0.f;
        #pragma unroll
        for (int k = 0; k < 16; k++) s += wpart[k];
        int rlo2 = sr - 45 < 0 ? 0 : sr - 45;
        int rhi2 = sr + 45 > 255 ? 255 : sr + 45;
        int clo2 = sc - 45 < 0 ? 0 : sc - 45;
        int chi2 = sc + 45 > 255 ? 255 : sc + 45;
        float area = (float)((rhi2 - rlo2 + 1) * (chi2 - clo2 + 1));
        s += (65536.0f - area) * c0log;
        g_partial[ch] = s;
    }
}

__global__ void k_final(float* __restrict__ out) {
    float s = 0.f;
    for (int k = 0; k < NCH; k++) s += g_partial[k];
    out[0] = 0.5f * s / 8388608.0f;
}

extern "C" void kernel_launch(void* const* d_in, const int* in_sizes, int n_in,
                              void* d_out, int out_size) {
    const float* cls = (const float*)d_in[0];
    const int* lab   = (const int*)d_in[1];
    const float4* seeds = (const float4*)d_in[2];

    cudaFuncSetAttribute(k_flood, cudaFuncAttributeMaxDynamicSharedMemorySize, SMEM_BYTES);

    k_init<<<1, 128>>>();
    k_seed_scan<<<1024, 256>>>(seeds);
    k_masks<<<1024, 256>>>(cls, lab);
    k_flood<<<128, 512, SMEM_BYTES>>>();
    k_final<<<1, 1>>>((float*)d_out);
}

// round 3
// speedup vs baseline: 2.6431x; 1.4159x over previous
#include <cuda_runtime.h>
#include <math.h>

// B=4, C=2, H=W=1024, DS=4 -> 256x256, NUM_SEEDS=32, 15 steps, pool 7x7.
#define NCH   128
#define RS    97            // active region: seed +/- 48
#define PITCH 112           // floats per row; col c stored at offset 4+c (left pad 4, right pad)
#define SMEM_BYTES (3 * RS * PITCH * 4)

__device__ float    g_road[4 * 256 * 256];
__device__ unsigned g_gtb[4 * 256 * 8];
__device__ int   g_sr[NCH];
__device__ int   g_sc[NCH];
__device__ int   g_scnt[NCH];   // zero-init; written 1 when seed found (<=1 writer/ch)
__device__ float g_sv[NCH];
__device__ float g_partial[NCH];
__device__ int   g_done;        // zero-init; reset by last block each call

// Fused prep: blocks [0,1024) build masks/gt-bits, blocks [1024,2048) scan seeds.
__global__ void k_prep(const float* __restrict__ cls, const int* __restrict__ lab,
                       const float4* __restrict__ seeds) {
    if (blockIdx.x < 1024) {
        int idx = blockIdx.x * 256 + threadIdx.x;       // < 262144 always
        int j = idx & 255, i = (idx >> 8) & 255, b = idx >> 16;
        const float* c0 = cls + (size_t)(b * 2 + 0) * 1048576;
        const float* c1 = cls + (size_t)(b * 2 + 1) * 1048576;
        int r1 = 4 * i + 1, r2 = 4 * i + 2, cc = 4 * j;
        float4 a0 = *(const float4*)(c0 + r1 * 1024 + cc);
        float4 a1 = *(const float4*)(c1 + r1 * 1024 + cc);
        float4 b0 = *(const float4*)(c0 + r2 * 1024 + cc);
        float4 b1 = *(const float4*)(c1 + r2 * 1024 + cc);
        float p1 = 1.f / (1.f + expf(a0.y - a1.y));
        float p2 = 1.f / (1.f + expf(a0.z - a1.z));
        float p3 = 1.f / (1.f + expf(b0.y - b1.y));
        float p4 = 1.f / (1.f + expf(b0.z - b1.z));
        g_road[idx] = 0.25f * (p1 + p2 + p3 + p4);
        int g = lab[((size_t)b * 1024 + 4 * i) * 1024 + 4 * j];
        unsigned bits = __ballot_sync(0xffffffffu, g != 0);
        if ((threadIdx.x & 31) == 0)
            g_gtb[((size_t)b * 256 + i) * 8 + (j >> 5)] = bits;
    } else {
        const int n4 = (4 * 32 * 256 * 256) / 4;
        for (int i = (blockIdx.x - 1024) * 256 + threadIdx.x; i < n4; i += 1024 * 256) {
            float4 v = seeds[i];
            if (v.x > 0.f || v.y > 0.f || v.z > 0.f || v.w > 0.f) {
                float vals[4] = {v.x, v.y, v.z, v.w};
                #pragma unroll
                for (int k = 0; k < 4; k++) if (vals[k] > 0.f) {
                    int idx = i * 4 + k;
                    int ch = idx >> 16;
                    // exactly one nonzero per channel by construction -> no atomics
                    g_sr[ch] = (idx >> 8) & 255;
                    g_sc[ch] = idx & 255;
                    g_sv[ch] = vals[k];
                    g_scnt[ch] = 1;
                }
            }
        }
    }
}

__device__ __forceinline__ unsigned getword(const unsigned* row, int start) {
    int w = start >> 5;
    int sh = start & 31;
    unsigned lo = ((unsigned)w < 8u) ? row[w] : 0u;
    unsigned hi = ((unsigned)(w + 1) < 8u) ? row[w + 1] : 0u;
    return __funnelshift_r(lo, hi, sh);
}
__device__ __forceinline__ uint4 bshl(uint4 v, int s) {
    return make_uint4(v.x << s, __funnelshift_l(v.x, v.y, s),
                      __funnelshift_l(v.y, v.z, s), __funnelshift_l(v.z, v.w, s));
}
__device__ __forceinline__ uint4 bshr(uint4 v, int s) {
    return make_uint4(__funnelshift_r(v.x, v.y, s), __funnelshift_r(v.y, v.z, s),
                      __funnelshift_r(v.z, v.w, s), v.w >> s);
}
__device__ __forceinline__ uint4 bor(uint4 a, uint4 b) {
    return make_uint4(a.x | b.x, a.y | b.y, a.z | b.z, a.w | b.w);
}
__device__ __forceinline__ float4 max4(float4 a, float4 b) {
    return make_float4(fmaxf(a.x, b.x), fmaxf(a.y, b.y), fmaxf(a.z, b.z), fmaxf(a.w, b.w));
}
__device__ __forceinline__ float4 min4(float4 a, float4 b) {
    return make_float4(fminf(a.x, b.x), fminf(a.y, b.y), fminf(a.z, b.z), fminf(a.w, b.w));
}

#define SM4(base, y, c) (*(float4*)((base) + (y) * PITCH + 4 + (c)))

__global__ void __launch_bounds__(512, 1) k_flood(float* __restrict__ out) {
    extern __shared__ float sm[];
    float* A  = sm;                    // pred state (zero-padded)
    float* Bt = sm + RS * PITCH;       // h-pass temp
    float* M  = sm + 2 * RS * PITCH;   // road mask crop
    __shared__ uint4 Gs[RS];
    __shared__ uint4 Gh[RS];
    __shared__ uint4 Gm[RS];
    __shared__ float wpart[16];
    __shared__ int   s_last;

    int ch  = blockIdx.x;
    int tid = threadIdx.x;
    int b   = ch >> 5;
    const float c0log = -logf(1.0f - 1e-7f);

    bool hasseed = (g_scnt[ch] != 0);
    if (!hasseed) {
        if (tid == 0) g_partial[ch] = 65536.0f * c0log;
    } else {
        int sr = g_sr[ch], sc = g_sc[ch];
        float sv = g_sv[ch];
        int gr0 = sr - 48, gc0 = sc - 48;

        // ---- init: zero A and M (incl pads), fill M crop + gt bits ----
        {
            float4 z4 = make_float4(0.f, 0.f, 0.f, 0.f);
            float4* A4 = (float4*)A;
            float4* M4 = (float4*)M;
            for (int i = tid; i < RS * PITCH / 4; i += 512) { A4[i] = z4; M4[i] = z4; }
        }
        if (tid < RS) {
            int gy = gr0 + tid;
            uint4 gm = make_uint4(0, 0, 0, 0);
            if ((unsigned)gy < 256u) {
                const unsigned* row = &g_gtb[((size_t)b * 256 + gy) * 8];
                gm.x = getword(row, gc0);
                gm.y = getword(row, gc0 + 32);
                gm.z = getword(row, gc0 + 64);
                gm.w = getword(row, gc0 + 96);
            }
            gm.w &= 1u;
            Gm[tid] = gm;
            Gs[tid] = make_uint4(0, 0, 0, 0);
        }
        __syncthreads();
        for (int idx = tid; idx < RS * RS; idx += 512) {
            int y = idx / RS, x = idx - y * RS;
            int gy = gr0 + y, gx = gc0 + x;
            float m = 0.f;
            if ((unsigned)gy < 256u && (unsigned)gx < 256u)
                m = g_road[(b << 16) + (gy << 8) + gx];
            M[y * PITCH + 4 + x] = m;
        }
        __syncthreads();
        if (tid == 0) {
            A[48 * PITCH + 4 + 48] = sv;
            if (sv > 0.f) Gs[48].y |= (1u << 16);
        }
        __syncthreads();

        for (int it = 0; it < 15; it++) {
            int R  = 3 * (it + 1);             // <= 45
            int lo = 48 - R, hi = 48 + R, W = 2 * R + 1;
            int lo8 = lo & ~7;
            int ng8 = ((hi + 3 - lo8) >> 3) + 1;   // cover cols up to >= hi+3
            int rlo = lo - 3, nrows = W + 6;

            // --- horizontal 7-max (vectorized): A -> Bt ---
            int totalH = nrows * ng8;
            for (int u = tid; u < totalH; u += 512) {
                int y = rlo + u / ng8;
                int g = u - (u / ng8) * ng8;
                int xb = lo8 + (g << 3);
                const float4* src = (const float4*)(A + y * PITCH + xb);  // col xb-4
                float4 v0 = src[0], v1 = src[1], v2 = src[2], v3 = src[3];
                float a[16] = {v0.x, v0.y, v0.z, v0.w, v1.x, v1.y, v1.z, v1.w,
                               v2.x, v2.y, v2.z, v2.w, v3.x, v3.y, v3.z, v3.w};
                float p[14], q[12];
                #pragma unroll
                for (int k = 1; k <= 13; k++) p[k] = fmaxf(a[k], a[k + 1]);
                #pragma unroll
                for (int k = 1; k <= 11; k++) q[k] = fmaxf(p[k], p[k + 2]);
                float4 o0, o1;
                o0.x = fmaxf(q[1], q[4]);  o0.y = fmaxf(q[2], q[5]);
                o0.z = fmaxf(q[3], q[6]);  o0.w = fmaxf(q[4], q[7]);
                o1.x = fmaxf(q[5], q[8]);  o1.y = fmaxf(q[6], q[9]);
                o1.z = fmaxf(q[7], q[10]); o1.w = fmaxf(q[8], q[11]);
                float4* dst = (float4*)(Bt + y * PITCH + 4 + xb);
                dst[0] = o0; dst[1] = o1;
            }
            // --- gt bitwise horizontal dilate ---
            if (tid < RS) {
                uint4 x = Gs[tid];
                uint4 d = bor(x, bor(bshl(x, 1), bshr(x, 1)));
                d = bor(d, bor(bshl(x, 2), bshr(x, 2)));
                d = bor(d, bor(bshl(x, 3), bshr(x, 3)));
                Gh[tid] = d;
            }
            __syncthreads();

            // --- vertical 7-max + min(mask) + seed (vectorized): Bt -> A ---
            int lo4 = lo & ~3;
            int ng4 = ((hi - lo4) >> 2) + 1;       // cols up to <= hi+3 (< h-pass range)
            int nb  = (W + 5) / 6;
            if (tid < ng4 * nb) {
                int g = tid % ng4, band = tid / ng4;
                int c4 = lo4 + (g << 2);
                int y0 = lo + band * 6;
                float4 w[7];
                #pragma unroll
                for (int k = 0; k < 6; k++) w[k] = SM4(Bt, y0 - 3 + k, c4);
                #pragma unroll
                for (int k = 0; k < 6; k++) {
                    int y = y0 + k;
                    if (y > hi) break;
                    w[6] = SM4(Bt, y + 3, c4);
                    float4 m = max4(max4(max4(w[0], w[1]), max4(w[2], w[3])),
                                    max4(max4(w[4], w[5]), w[6]));
                    float4 val = min4(m, SM4(M, y, c4));
                    if (y == 48 && c4 == 48) val.x = fmaxf(val.x, sv);
                    SM4(A, y, c4) = val;
                    #pragma unroll
                    for (int j = 0; j < 6; j++) w[j] = w[j + 1];
                }
            }
            // --- gt bitwise vertical dilate + AND mask + seed ---
            if (tid < RS) {
                int y = tid;
                int ym3 = y - 3 < 0 ? 0 : y - 3;
                int yp3 = y + 3 > 96 ? 96 : y + 3;
                uint4 acc = Gh[ym3];
                for (int yy = ym3 + 1; yy <= yp3; yy++) acc = bor(acc, Gh[yy]);
                acc.x &= Gm[y].x; acc.y &= Gm[y].y; acc.z &= Gm[y].z; acc.w &= Gm[y].w;
                if (y == 48 && sv > 0.f) acc.y |= (1u << 16);
                Gs[y] = acc;
            }
            __syncthreads();
        }

        // ---- fused BCE over the +/-45 in-image box ----
        float local = 0.f;
        for (int idx = tid; idx < RS * RS; idx += 512) {
            int y = idx / RS, x = idx - y * RS;
            if (y < 3 || y > 93 || x < 3 || x > 93) continue;
            int gy = gr0 + y, gx = gc0 + x;
            if ((unsigned)gy >= 256u || (unsigned)gx >= 256u) continue;
            float pv = A[y * PITCH + 4 + x];
            pv = fminf(fmaxf(pv, 1e-7f), 1.0f - 1e-7f);
            uint4 gw = Gs[y];
            int ws = x >> 5;
            unsigned word = ws == 0 ? gw.x : ws == 1 ? gw.y : ws == 2 ? gw.z : gw.w;
            unsigned gbit = (word >> (x & 31)) & 1u;
            float t = gbit ? pv : (1.0f - pv);
            local -= __logf(t);
        }

        #pragma unroll
        for (int off = 16; off; off >>= 1)
            local += __shfl_down_sync(0xffffffffu, local, off);
        if ((tid & 31) == 0) wpart[tid >> 5] = local;
        __syncthreads();
        if (tid == 0) {
            float s = 0.f;
            #pragma unroll
            for (int k = 0; k < 16; k++) s += wpart[k];
            int rlo2 = sr - 45 < 0 ? 0 : sr - 45;
            int rhi2 = sr + 45 > 255 ? 255 : sr + 45;
            int clo2 = sc - 45 < 0 ? 0 : sc - 45;
            int chi2 = sc + 45 > 255 ? 255 : sc + 45;
            float area = (float)((rhi2 - rlo2 + 1) * (chi2 - clo2 + 1));
            s += (65536.0f - area) * c0log;
            g_partial[ch] = s;
        }
    }

    // ---- last-block finalize (replaces k_final launch) ----
    if (tid == 0) {
        __threadfence();
        int old = atomicAdd(&g_done, 1);
        s_last = (old == NCH - 1);
    }
    __syncthreads();
    if (s_last && tid < 32) {
        float v = g_partial[tid] + g_partial[tid + 32] +
                  g_partial[tid + 64] + g_partial[tid + 96];
        #pragma unroll
        for (int off = 16; off; off >>= 1)
            v += __shfl_down_sync(0xffffffffu, v, off);
        if (tid == 0) {
            out[0] = 0.5f * v / 8388608.0f;
            g_done = 0;                      // reset for next replay
        }
    }
}

extern "C" void kernel_launch(void* const* d_in, const int* in_sizes, int n_in,
                              void* d_out, int out_size) {
    const float* cls = (const float*)d_in[0];
    const int* lab   = (const int*)d_in[1];
    const float4* seeds = (const float4*)d_in[2];

    cudaFuncSetAttribute(k_flood, cudaFuncAttributeMaxDynamicSharedMemorySize, SMEM_BYTES);

    k_prep<<<2048, 256>>>(cls, lab, seeds);
    k_flood<<<128, 512, SMEM_BYTES>>>((float*)d_out);
}

// round 4
// speedup vs baseline: 2.7718x; 1.0487x over previous
#include <cuda_runtime.h>
#include <math.h>

// B=4, C=2, H=W=1024, DS=4 -> 256x256, NUM_SEEDS=32, 15 steps, pool 7x7.
#define NCH   128
#define RS    97            // active region: seed +/- 48
#define PITCH 112           // floats/row; col c at offset 4+c (left pad 4, right pad)
#define SMEM_BYTES (3 * RS * PITCH * 4)

__device__ float    g_road[4 * 256 * 256];
__device__ unsigned g_gtb[4 * 256 * 8];
__device__ int   g_sr[NCH];
__device__ int   g_sc[NCH];
__device__ int   g_scnt[NCH];
__device__ float g_sv[NCH];
__device__ float g_partial[NCH];
__device__ int   g_done;

__global__ void k_prep(const float* __restrict__ cls, const int* __restrict__ lab,
                       const float4* __restrict__ seeds) {
    if (blockIdx.x < 1024) {
        int idx = blockIdx.x * 256 + threadIdx.x;
        int j = idx & 255, i = (idx >> 8) & 255, b = idx >> 16;
        const float* c0 = cls + (size_t)(b * 2 + 0) * 1048576;
        const float* c1 = cls + (size_t)(b * 2 + 1) * 1048576;
        int r1 = 4 * i + 1, r2 = 4 * i + 2, cc = 4 * j;
        float4 a0 = *(const float4*)(c0 + r1 * 1024 + cc);
        float4 a1 = *(const float4*)(c1 + r1 * 1024 + cc);
        float4 b0 = *(const float4*)(c0 + r2 * 1024 + cc);
        float4 b1 = *(const float4*)(c1 + r2 * 1024 + cc);
        float p1 = 1.f / (1.f + expf(a0.y - a1.y));
        float p2 = 1.f / (1.f + expf(a0.z - a1.z));
        float p3 = 1.f / (1.f + expf(b0.y - b1.y));
        float p4 = 1.f / (1.f + expf(b0.z - b1.z));
        g_road[idx] = 0.25f * (p1 + p2 + p3 + p4);
        int g = lab[((size_t)b * 1024 + 4 * i) * 1024 + 4 * j];
        unsigned bits = __ballot_sync(0xffffffffu, g != 0);
        if ((threadIdx.x & 31) == 0)
            g_gtb[((size_t)b * 256 + i) * 8 + (j >> 5)] = bits;
    } else {
        const int n4 = (4 * 32 * 256 * 256) / 4;
        for (int i = (blockIdx.x - 1024) * 256 + threadIdx.x; i < n4; i += 1024 * 256) {
            float4 v = seeds[i];
            if (v.x > 0.f || v.y > 0.f || v.z > 0.f || v.w > 0.f) {
                float vals[4] = {v.x, v.y, v.z, v.w};
                #pragma unroll
                for (int k = 0; k < 4; k++) if (vals[k] > 0.f) {
                    int idx = i * 4 + k;
                    int ch = idx >> 16;
                    g_sr[ch] = (idx >> 8) & 255;
                    g_sc[ch] = idx & 255;
                    g_sv[ch] = vals[k];
                    g_scnt[ch] = 1;
                }
            }
        }
    }
}

__device__ __forceinline__ unsigned getword(const unsigned* row, int start) {
    int w = start >> 5;
    int sh = start & 31;
    unsigned lo = ((unsigned)w < 8u) ? row[w] : 0u;
    unsigned hi = ((unsigned)(w + 1) < 8u) ? row[w + 1] : 0u;
    return __funnelshift_r(lo, hi, sh);
}
__device__ __forceinline__ uint4 bshl(uint4 v, int s) {
    return make_uint4(v.x << s, __funnelshift_l(v.x, v.y, s),
                      __funnelshift_l(v.y, v.z, s), __funnelshift_l(v.z, v.w, s));
}
__device__ __forceinline__ uint4 bshr(uint4 v, int s) {
    return make_uint4(__funnelshift_r(v.x, v.y, s), __funnelshift_r(v.y, v.z, s),
                      __funnelshift_r(v.z, v.w, s), v.w >> s);
}
__device__ __forceinline__ uint4 bor(uint4 a, uint4 b) {
    return make_uint4(a.x | b.x, a.y | b.y, a.z | b.z, a.w | b.w);
}
__device__ __forceinline__ float4 max4(float4 a, float4 b) {
    return make_float4(fmaxf(a.x, b.x), fmaxf(a.y, b.y), fmaxf(a.z, b.z), fmaxf(a.w, b.w));
}
__device__ __forceinline__ float4 min4(float4 a, float4 b) {
    return make_float4(fminf(a.x, b.x), fminf(a.y, b.y), fminf(a.z, b.z), fminf(a.w, b.w));
}

#define SM4(base, y, c) (*(float4*)((base) + (y) * PITCH + 4 + (c)))

__global__ void __launch_bounds__(512, 1) k_flood(float* __restrict__ out) {
    extern __shared__ float sm[];
    float* A  = sm;
    float* Bt = sm + RS * PITCH;
    float* M  = sm + 2 * RS * PITCH;
    __shared__ uint4 Gs[RS];
    __shared__ uint4 Gh[RS];
    __shared__ uint4 Gm[RS];
    __shared__ float wpart[16];
    __shared__ int   s_last;

    int ch  = blockIdx.x;
    unsigned tid = threadIdx.x;
    int b   = ch >> 5;
    const float c0log = -logf(1.0f - 1e-7f);

    bool hasseed = (g_scnt[ch] != 0);
    if (!hasseed) {
        if (tid == 0) g_partial[ch] = 65536.0f * c0log;
    } else {
        int sr = g_sr[ch], sc = g_sc[ch];
        float sv = g_sv[ch];
        int gr0 = sr - 48, gc0 = sc - 48;

        // ---- init ----
        {
            float4 z4 = make_float4(0.f, 0.f, 0.f, 0.f);
            float4* A4 = (float4*)A;
            float4* M4 = (float4*)M;
            for (int i = tid; i < RS * PITCH / 4; i += 512) { A4[i] = z4; M4[i] = z4; }
        }
        if (tid >= 415) {
            int gy2 = tid - 415;              // 0..96
            int gy = gr0 + gy2;
            uint4 gm = make_uint4(0, 0, 0, 0);
            if ((unsigned)gy < 256u) {
                const unsigned* row = &g_gtb[((size_t)b * 256 + gy) * 8];
                gm.x = getword(row, gc0);
                gm.y = getword(row, gc0 + 32);
                gm.z = getword(row, gc0 + 64);
                gm.w = getword(row, gc0 + 96);
            }
            gm.w &= 1u;
            Gm[gy2] = gm;
            Gs[gy2] = make_uint4(0, 0, 0, 0);
        }
        __syncthreads();
        for (unsigned idx = tid; idx < RS * RS; idx += 512) {
            int y = idx / RS, x = idx - y * RS;
            int gy = gr0 + y, gx = gc0 + x;
            float m = 0.f;
            if ((unsigned)gy < 256u && (unsigned)gx < 256u)
                m = g_road[(b << 16) + (gy << 8) + gx];
            M[y * PITCH + 4 + x] = m;
        }
        __syncthreads();
        if (tid == 0) {
            A[48 * PITCH + 4 + 48] = sv;
            if (sv > 0.f) Gs[48].y |= (1u << 16);
        }
        __syncthreads();

        for (int it = 0; it < 15; it++) {
            int R  = 3 * (it + 1);            // <= 45
            int lo = 48 - R, hi = 48 + R;
            int rlo = lo - 3;
            unsigned NU = (unsigned)(2 * R + 7) * 13;   // nrows * 13

            // --- horizontal 7-max, full-width rows [rlo, hi+3] : A -> Bt ---
            for (unsigned u = tid; u < NU; u += 512) {
                unsigned yy = u / 13u;                   // const-div
                unsigned g  = u - yy * 13u;
                int y  = rlo + (int)yy;
                int xb = (int)(g << 3);                  // output cols xb..xb+7
                const float4* src = (const float4*)(A + y * PITCH + xb); // col xb-4
                float4 v0 = src[0], v1 = src[1], v2 = src[2], v3 = src[3];
                float a[16] = {v0.x, v0.y, v0.z, v0.w, v1.x, v1.y, v1.z, v1.w,
                               v2.x, v2.y, v2.z, v2.w, v3.x, v3.y, v3.z, v3.w};
                float p[14], q[12];
                #pragma unroll
                for (int k = 1; k <= 13; k++) p[k] = fmaxf(a[k], a[k + 1]);
                #pragma unroll
                for (int k = 1; k <= 11; k++) q[k] = fmaxf(p[k], p[k + 2]);
                float4 o0, o1;
                o0.x = fmaxf(q[1], q[4]);  o0.y = fmaxf(q[2], q[5]);
                o0.z = fmaxf(q[3], q[6]);  o0.w = fmaxf(q[4], q[7]);
                o1.x = fmaxf(q[5], q[8]);  o1.y = fmaxf(q[6], q[9]);
                o1.z = fmaxf(q[7], q[10]); o1.w = fmaxf(q[8], q[11]);
                float4* dst = (float4*)(Bt + y * PITCH + 4 + xb);
                dst[0] = o0; dst[1] = o1;
            }
            // --- gt horizontal dilate on warps 13-15 ---
            if (tid >= 415) {
                int gy2 = tid - 415;
                uint4 x = Gs[gy2];
                uint4 d = bor(x, bor(bshl(x, 1), bshr(x, 1)));
                d = bor(d, bor(bshl(x, 2), bshr(x, 2)));
                d = bor(d, bor(bshl(x, 3), bshr(x, 3)));
                Gh[gy2] = d;
            }
            __syncthreads();

            // --- vertical 7-max + min(mask) + seed : Bt -> A (single-shot) ---
            {
                unsigned g2   = tid % 25u;               // const-div
                unsigned band = tid / 25u;
                int c4 = (int)(g2 << 2);
                int y0 = lo + (int)band * 6;
                int glo = lo >> 2, ghi = hi >> 2;
                if ((int)g2 >= glo && (int)g2 <= ghi && y0 <= hi) {
                    float4 w[7];
                    #pragma unroll
                    for (int k = 0; k < 6; k++) w[k] = SM4(Bt, y0 - 3 + k, c4);
                    #pragma unroll
                    for (int k = 0; k < 6; k++) {
                        int y = y0 + k;
                        if (y > hi) break;
                        w[6] = SM4(Bt, y + 3, c4);
                        float4 m = max4(max4(max4(w[0], w[1]), max4(w[2], w[3])),
                                        max4(max4(w[4], w[5]), w[6]));
                        float4 val = min4(m, SM4(M, y, c4));
                        if (y == 48 && c4 == 48) val.x = fmaxf(val.x, sv);
                        SM4(A, y, c4) = val;
                        #pragma unroll
                        for (int j = 0; j < 6; j++) w[j] = w[j + 1];
                    }
                }
            }
            // --- gt vertical dilate + AND mask + seed ---
            if (tid >= 415) {
                int y = tid - 415;
                int ym3 = y - 3 < 0 ? 0 : y - 3;
                int yp3 = y + 3 > 96 ? 96 : y + 3;
                uint4 acc = Gh[ym3];
                for (int yy = ym3 + 1; yy <= yp3; yy++) acc = bor(acc, Gh[yy]);
                acc.x &= Gm[y].x; acc.y &= Gm[y].y; acc.z &= Gm[y].z; acc.w &= Gm[y].w;
                if (y == 48 && sv > 0.f) acc.y |= (1u << 16);
                Gs[y] = acc;
            }
            __syncthreads();
        }

        // ---- fused BCE over the +/-45 in-image box (float4 + fast log) ----
        float local = 0.f;
        for (unsigned u = tid; u < 97u * 25u; u += 512) {
            unsigned y = u / 25u;                        // const-div
            unsigned g = u - y * 25u;
            if (y < 3u || y > 93u) continue;
            int c4 = (int)(g << 2);
            float4 pv4 = SM4(A, (int)y, c4);
            uint4 gw = Gs[y];
            float pv[4] = {pv4.x, pv4.y, pv4.z, pv4.w};
            #pragma unroll
            for (int k = 0; k < 4; k++) {
                int x = c4 + k;
                if (x < 3 || x > 93) continue;
                int gy = gr0 + (int)y, gx = gc0 + x;
                if ((unsigned)gy >= 256u || (unsigned)gx >= 256u) continue;
                float p = fminf(fmaxf(pv[k], 1e-7f), 1.0f - 1e-7f);
                int ws = x >> 5;
                unsigned word = ws == 0 ? gw.x : ws == 1 ? gw.y : ws == 2 ? gw.z : gw.w;
                float t = ((word >> (x & 31)) & 1u) ? p : (1.0f - p);
                local -= __logf(t);
            }
        }

        #pragma unroll
        for (int off = 16; off; off >>= 1)
            local += __shfl_down_sync(0xffffffffu, local, off);
        if ((tid & 31) == 0) wpart[tid >> 5] = local;
        __syncthreads();
        if (tid == 0) {
            float s = 0.f;
            #pragma unroll
            for (int k = 0; k < 16; k++) s += wpart[k];
            int rlo2 = sr - 45 < 0 ? 0 : sr - 45;
            int rhi2 = sr + 45 > 255 ? 255 : sr + 45;
            int clo2 = sc - 45 < 0 ? 0 : sc - 45;
            int chi2 = sc + 45 > 255 ? 255 : sc + 45;
            float area = (float)((rhi2 - rlo2 + 1) * (chi2 - clo2 + 1));
            s += (65536.0f - area) * c0log;
            g_partial[ch] = s;
        }
    }

    // ---- last-block finalize ----
    if (tid == 0) {
        __threadfence();
        int old = atomicAdd(&g_done, 1);
        s_last = (old == NCH - 1);
    }
    __syncthreads();
    if (s_last && tid < 32) {
        float v = g_partial[tid] + g_partial[tid + 32] +
                  g_partial[tid + 64] + g_partial[tid + 96];
        #pragma unroll
        for (int off = 16; off; off >>= 1)
            v += __shfl_down_sync(0xffffffffu, v, off);
        if (tid == 0) {
            out[0] = 0.5f * v / 8388608.0f;
            g_done = 0;
        }
    }
}

extern "C" void kernel_launch(void* const* d_in, const int* in_sizes, int n_in,
                              void* d_out, int out_size) {
    const float* cls = (const float*)d_in[0];
    const int* lab   = (const int*)d_in[1];
    const float4* seeds = (const float4*)d_in[2];

    cudaFuncSetAttribute(k_flood, cudaFuncAttributeMaxDynamicSharedMemorySize, SMEM_BYTES);

    k_prep<<<2048, 256>>>(cls, lab, seeds);
    k_flood<<<128, 512, SMEM_BYTES>>>((float*)d_out);
}

// round 5
// speedup vs baseline: 2.9449x; 1.0624x over previous
#include <cuda_runtime.h>
#include <math.h>

// B=4, C=2, H=W=1024, DS=4 -> 256x256, NUM_SEEDS=32, 15 steps, pool 7x7.
#define NCH   128
#define RS    97            // active region: seed +/- 48
#define PITCH 116           // floats/row; col c at offset 4+c. 116%32=20 -> conflict-free
#define ARR   (RS * PITCH + 16)   // +16 slack for h-pass row-end overread
#define SMEM_BYTES (3 * ARR * 4)

__device__ float    g_road[4 * 256 * 256];
__device__ unsigned g_gtb[4 * 256 * 8];
__device__ int   g_sr[NCH];
__device__ int   g_sc[NCH];
__device__ int   g_scnt[NCH];
__device__ float g_sv[NCH];
__device__ float g_partial[NCH];
__device__ int   g_done;

__global__ void k_prep(const float* __restrict__ cls, const int* __restrict__ lab,
                       const float4* __restrict__ seeds) {
    if (blockIdx.x < 1024) {
        int idx = blockIdx.x * 256 + threadIdx.x;
        int j = idx & 255, i = (idx >> 8) & 255, b = idx >> 16;
        const float* c0 = cls + (size_t)(b * 2 + 0) * 1048576;
        const float* c1 = cls + (size_t)(b * 2 + 1) * 1048576;
        int r1 = 4 * i + 1, r2 = 4 * i + 2, cc = 4 * j;
        float4 a0 = *(const float4*)(c0 + r1 * 1024 + cc);
        float4 a1 = *(const float4*)(c1 + r1 * 1024 + cc);
        float4 b0 = *(const float4*)(c0 + r2 * 1024 + cc);
        float4 b1 = *(const float4*)(c1 + r2 * 1024 + cc);
        float p1 = 1.f / (1.f + expf(a0.y - a1.y));
        float p2 = 1.f / (1.f + expf(a0.z - a1.z));
        float p3 = 1.f / (1.f + expf(b0.y - b1.y));
        float p4 = 1.f / (1.f + expf(b0.z - b1.z));
        g_road[idx] = 0.25f * (p1 + p2 + p3 + p4);
        int g = lab[((size_t)b * 1024 + 4 * i) * 1024 + 4 * j];
        unsigned bits = __ballot_sync(0xffffffffu, g != 0);
        if ((threadIdx.x & 31) == 0)
            g_gtb[((size_t)b * 256 + i) * 8 + (j >> 5)] = bits;
    } else {
        const int n4 = (4 * 32 * 256 * 256) / 4;
        for (int i = (blockIdx.x - 1024) * 256 + threadIdx.x; i < n4; i += 1024 * 256) {
            float4 v = seeds[i];
            if (v.x > 0.f || v.y > 0.f || v.z > 0.f || v.w > 0.f) {
                float vals[4] = {v.x, v.y, v.z, v.w};
                #pragma unroll
                for (int k = 0; k < 4; k++) if (vals[k] > 0.f) {
                    int idx = i * 4 + k;
                    int ch = idx >> 16;
                    g_sr[ch] = (idx >> 8) & 255;
                    g_sc[ch] = idx & 255;
                    g_sv[ch] = vals[k];
                    g_scnt[ch] = 1;
                }
            }
        }
    }
}

__device__ __forceinline__ unsigned getword(const unsigned* row, int start) {
    int w = start >> 5;
    int sh = start & 31;
    unsigned lo = ((unsigned)w < 8u) ? row[w] : 0u;
    unsigned hi = ((unsigned)(w + 1) < 8u) ? row[w + 1] : 0u;
    return __funnelshift_r(lo, hi, sh);
}
__device__ __forceinline__ uint4 bshl(uint4 v, int s) {
    return make_uint4(v.x << s, __funnelshift_l(v.x, v.y, s),
                      __funnelshift_l(v.y, v.z, s), __funnelshift_l(v.z, v.w, s));
}
__device__ __forceinline__ uint4 bshr(uint4 v, int s) {
    return make_uint4(__funnelshift_r(v.x, v.y, s), __funnelshift_r(v.y, v.z, s),
                      __funnelshift_r(v.z, v.w, s), v.w >> s);
}
__device__ __forceinline__ uint4 bor(uint4 a, uint4 b) {
    return make_uint4(a.x | b.x, a.y | b.y, a.z | b.z, a.w | b.w);
}
__device__ __forceinline__ float4 max4(float4 a, float4 b) {
    return make_float4(fmaxf(a.x, b.x), fmaxf(a.y, b.y), fmaxf(a.z, b.z), fmaxf(a.w, b.w));
}
__device__ __forceinline__ float4 min4(float4 a, float4 b) {
    return make_float4(fminf(a.x, b.x), fminf(a.y, b.y), fminf(a.z, b.z), fminf(a.w, b.w));
}

#define SM4(base, y, c) (*(float4*)((base) + (y) * PITCH + 4 + (c)))

__global__ void __launch_bounds__(512, 1) k_flood(float* __restrict__ out) {
    extern __shared__ float sm[];
    float* A  = sm;
    float* Bt = sm + ARR;
    float* M  = sm + 2 * ARR;
    __shared__ uint4 Gs[RS];
    __shared__ uint4 Gh[RS];
    __shared__ uint4 Gm[RS];
    __shared__ float wpart[16];
    __shared__ int   s_last;

    int ch  = blockIdx.x;
    unsigned tid = threadIdx.x;
    int b   = ch >> 5;
    const float c0log = -logf(1.0f - 1e-7f);

    bool hasseed = (g_scnt[ch] != 0);
    if (!hasseed) {
        if (tid == 0) g_partial[ch] = 65536.0f * c0log;
    } else {
        int sr = g_sr[ch], sc = g_sc[ch];
        float sv = g_sv[ch];
        int gr0 = sr - 48, gc0 = sc - 48;

        // ---- init: zero A,M (incl pads + slack), mask crop, gt bits ----
        {
            float4 z4 = make_float4(0.f, 0.f, 0.f, 0.f);
            float4* A4 = (float4*)A;
            float4* M4 = (float4*)M;
            for (int i = tid; i < ARR / 4; i += 512) { A4[i] = z4; M4[i] = z4; }
        }
        if (tid >= 415) {
            int gy2 = tid - 415;              // 0..96
            int gy = gr0 + gy2;
            uint4 gm = make_uint4(0, 0, 0, 0);
            if ((unsigned)gy < 256u) {
                const unsigned* row = &g_gtb[((size_t)b * 256 + gy) * 8];
                gm.x = getword(row, gc0);
                gm.y = getword(row, gc0 + 32);
                gm.z = getword(row, gc0 + 64);
                gm.w = getword(row, gc0 + 96);
            }
            gm.w &= 1u;
            Gm[gy2] = gm;
            Gs[gy2] = make_uint4(0, 0, 0, 0);
        }
        __syncthreads();
        for (unsigned idx = tid; idx < RS * RS; idx += 512) {
            int y = idx / RS, x = idx - y * RS;
            int gy = gr0 + y, gx = gc0 + x;
            float m = 0.f;
            if ((unsigned)gy < 256u && (unsigned)gx < 256u)
                m = g_road[(b << 16) + (gy << 8) + gx];
            M[y * PITCH + 4 + x] = m;
        }
        __syncthreads();
        if (tid == 0) {
            A[48 * PITCH + 4 + 48] = sv;
            if (sv > 0.f) Gs[48].y |= (1u << 16);
        }
        __syncthreads();

        for (int it = 0; it < 15; it++) {
            int R  = 3 * (it + 1);            // <= 45
            int lo = 48 - R, hi = 48 + R;
            int rlo = lo - 3, rhi = hi + 3;   // always within [0,96]

            // --- horizontal 7-max, 16-output units: A -> Bt ---
            // unit u: g = u/103 (col group, 16 cols), y = u%103 (row)
            for (unsigned u = tid; u < 7u * 103u; u += 512) {
                unsigned g = u / 103u;                   // const-div
                int y = (int)(u - g * 103u);
                int xb = (int)(g << 4);
                if (y < rlo || y > rhi) continue;
                if (xb > rhi || xb + 15 < rlo) continue; // group skip
                const float4* src = (const float4*)(A + y * PITCH + xb); // col xb-4
                float a[24];
                #pragma unroll
                for (int v = 0; v < 6; v++) {
                    float4 t = src[v];
                    a[4 * v] = t.x; a[4 * v + 1] = t.y; a[4 * v + 2] = t.z; a[4 * v + 3] = t.w;
                }
                float p[22], q[20];
                #pragma unroll
                for (int k = 1; k <= 21; k++) p[k] = fmaxf(a[k], a[k + 1]);
                #pragma unroll
                for (int k = 1; k <= 19; k++) q[k] = fmaxf(p[k], p[k + 2]);
                float4 o[4];
                #pragma unroll
                for (int k = 0; k < 16; k++)
                    ((float*)o)[k] = fmaxf(q[k + 1], q[k + 4]);
                float4* dst = (float4*)(Bt + y * PITCH + 4 + xb);
                dst[0] = o[0]; dst[1] = o[1]; dst[2] = o[2]; dst[3] = o[3];
            }
            // --- gt horizontal dilate (warps 13-15 region) ---
            if (tid >= 415) {
                int gy2 = tid - 415;
                uint4 x = Gs[gy2];
                uint4 d = bor(x, bor(bshl(x, 1), bshr(x, 1)));
                d = bor(d, bor(bshl(x, 2), bshr(x, 2)));
                d = bor(d, bor(bshl(x, 3), bshr(x, 3)));
                Gh[gy2] = d;
            }
            __syncthreads();

            // --- vertical 7-max (van Herk) + min(mask) + seed : Bt -> A ---
            {
                unsigned g2   = tid % 25u;               // const-div
                unsigned band = tid / 25u;
                int c4 = (int)(g2 << 2);
                int y0 = lo + (int)band * 6;
                if ((int)g2 >= (lo >> 2) && (int)g2 <= (hi >> 2) && y0 <= hi) {
                    float4 r[12];
                    #pragma unroll
                    for (int i = 0; i < 12; i++) {
                        int ry = y0 - 3 + i;
                        ry = ry > rhi ? rhi : ry;
                        r[i] = SM4(Bt, ry, c4);
                    }
                    float4 S[7];
                    S[6] = r[6];
                    #pragma unroll
                    for (int i = 5; i >= 0; i--) S[i] = max4(r[i], S[i + 1]);
                    float4 P[5];
                    P[0] = r[7];
                    #pragma unroll
                    for (int j = 1; j < 5; j++) P[j] = max4(P[j - 1], r[7 + j]);
                    #pragma unroll
                    for (int k = 0; k < 6; k++) {
                        int y = y0 + k;
                        if (y > hi) break;
                        float4 m = (k == 0) ? S[0] : max4(S[k], P[k - 1]);
                        float4 val = min4(m, SM4(M, y, c4));
                        if (y == 48 && c4 == 48) val.x = fmaxf(val.x, sv);
                        SM4(A, y, c4) = val;
                    }
                }
            }
            // --- gt vertical dilate + AND mask + seed ---
            if (tid >= 415) {
                int y = tid - 415;
                int ym3 = y - 3 < 0 ? 0 : y - 3;
                int yp3 = y + 3 > 96 ? 96 : y + 3;
                uint4 acc = Gh[ym3];
                for (int yy = ym3 + 1; yy <= yp3; yy++) acc = bor(acc, Gh[yy]);
                acc.x &= Gm[y].x; acc.y &= Gm[y].y; acc.z &= Gm[y].z; acc.w &= Gm[y].w;
                if (y == 48 && sv > 0.f) acc.y |= (1u << 16);
                Gs[y] = acc;
            }
            __syncthreads();
        }

        // ---- fused BCE, bounds hoisted ----
        int ylo = 3 > -gr0 ? 3 : -gr0;
        int yhi = 93 < 255 - gr0 ? 93 : 255 - gr0;
        int xlo = 3 > -gc0 ? 3 : -gc0;
        int xhi = 93 < 255 - gc0 ? 93 : 255 - gc0;
        int nrows2 = yhi - ylo + 1;
        float local = 0.f;
        for (unsigned u = tid; u < (unsigned)nrows2 * 25u; u += 512) {
            unsigned yy = u / 25u;                       // const-div
            unsigned g = u - yy * 25u;
            int y = ylo + (int)yy;
            int c4 = (int)(g << 2);
            if (c4 + 3 < xlo || c4 > xhi) continue;
            float4 pv4 = SM4(A, y, c4);
            uint4 gw = Gs[y];
            float pv[4] = {pv4.x, pv4.y, pv4.z, pv4.w};
            #pragma unroll
            for (int k = 0; k < 4; k++) {
                int x = c4 + k;
                if (x < xlo || x > xhi) continue;
                float p = fminf(fmaxf(pv[k], 1e-7f), 1.0f - 1e-7f);
                int ws = x >> 5;
                unsigned word = ws == 0 ? gw.x : ws == 1 ? gw.y : ws == 2 ? gw.z : gw.w;
                float t = ((word >> (x & 31)) & 1u) ? p : (1.0f - p);
                local -= __logf(t);
            }
        }

        #pragma unroll
        for (int off = 16; off; off >>= 1)
            local += __shfl_down_sync(0xffffffffu, local, off);
        if ((tid & 31) == 0) wpart[tid >> 5] = local;
        __syncthreads();
        if (tid == 0) {
            float s = 0.f;
            #pragma unroll
            for (int k = 0; k < 16; k++) s += wpart[k];
            float area = (float)((yhi - ylo + 1) * (xhi - xlo + 1));
            s += (65536.0f - area) * c0log;
            g_partial[ch] = s;
        }
    }

    // ---- last-block finalize ----
    if (tid == 0) {
        __threadfence();
        int old = atomicAdd(&g_done, 1);
        s_last = (old == NCH - 1);
    }
    __syncthreads();
    if (s_last && tid < 32) {
        float v = g_partial[tid] + g_partial[tid + 32] +
                  g_partial[tid + 64] + g_partial[tid + 96];
        #pragma unroll
        for (int off = 16; off; off >>= 1)
            v += __shfl_down_sync(0xffffffffu, v, off);
        if (tid == 0) {
            out[0] = 0.5f * v / 8388608.0f;
            g_done = 0;
        }
    }
}

extern "C" void kernel_launch(void* const* d_in, const int* in_sizes, int n_in,
                              void* d_out, int out_size) {
    const float* cls = (const float*)d_in[0];
    const int* lab   = (const int*)d_in[1];
    const float4* seeds = (const float4*)d_in[2];

    cudaFuncSetAttribute(k_flood, cudaFuncAttributeMaxDynamicSharedMemorySize, SMEM_BYTES);

    k_prep<<<2048, 256>>>(cls, lab, seeds);
    k_flood<<<128, 512, SMEM_BYTES>>>((float*)d_out);
}

// round 6
// speedup vs baseline: 3.2288x; 1.0964x over previous
#include <cuda_runtime.h>
#include <cuda_fp16.h>
#include <math.h>

// B=4, C=2, H=W=1024, DS=4 -> 256x256, NUM_SEEDS=32, 15 steps, pool 7x7.
#define NCH   128
#define RS    97              // active region: seed +/- 48
#define PH    136             // halfs per row (272B == 16 mod 128 -> conflict-free LDS.128)
#define PADC  8               // col c stored at half-offset PADC + c
#define ARRH  (RS * PH + 16)  // +16 halfs slack for h-pass tail overread
#define SMEM_BYTES (3 * ARRH * 2)

__device__ float    g_road[4 * 256 * 256];
__device__ unsigned g_gtb[4 * 256 * 8];
__device__ int   g_sr[NCH];
__device__ int   g_sc[NCH];
__device__ int   g_scnt[NCH];
__device__ float g_sv[NCH];
__device__ float g_partial[NCH];
__device__ int   g_done;

__global__ void k_prep(const float* __restrict__ cls, const int* __restrict__ lab,
                       const float4* __restrict__ seeds) {
    if (blockIdx.x < 1024) {
        int idx = blockIdx.x * 256 + threadIdx.x;
        int j = idx & 255, i = (idx >> 8) & 255, b = idx >> 16;
        const float* c0 = cls + (size_t)(b * 2 + 0) * 1048576;
        const float* c1 = cls + (size_t)(b * 2 + 1) * 1048576;
        int r1 = 4 * i + 1, r2 = 4 * i + 2, cc = 4 * j;
        float4 a0 = *(const float4*)(c0 + r1 * 1024 + cc);
        float4 a1 = *(const float4*)(c1 + r1 * 1024 + cc);
        float4 b0 = *(const float4*)(c0 + r2 * 1024 + cc);
        float4 b1 = *(const float4*)(c1 + r2 * 1024 + cc);
        float p1 = 1.f / (1.f + expf(a0.y - a1.y));
        float p2 = 1.f / (1.f + expf(a0.z - a1.z));
        float p3 = 1.f / (1.f + expf(b0.y - b1.y));
        float p4 = 1.f / (1.f + expf(b0.z - b1.z));
        g_road[idx] = 0.25f * (p1 + p2 + p3 + p4);
        int g = lab[((size_t)b * 1024 + 4 * i) * 1024 + 4 * j];
        unsigned bits = __ballot_sync(0xffffffffu, g != 0);
        if ((threadIdx.x & 31) == 0)
            g_gtb[((size_t)b * 256 + i) * 8 + (j >> 5)] = bits;
    } else {
        const int n4 = (4 * 32 * 256 * 256) / 4;
        for (int i = (blockIdx.x - 1024) * 256 + threadIdx.x; i < n4; i += 1024 * 256) {
            float4 v = seeds[i];
            if (v.x > 0.f || v.y > 0.f || v.z > 0.f || v.w > 0.f) {
                float vals[4] = {v.x, v.y, v.z, v.w};
                #pragma unroll
                for (int k = 0; k < 4; k++) if (vals[k] > 0.f) {
                    int idx = i * 4 + k;
                    int ch = idx >> 16;
                    g_sr[ch] = (idx >> 8) & 255;
                    g_sc[ch] = idx & 255;
                    g_sv[ch] = vals[k];
                    g_scnt[ch] = 1;
                }
            }
        }
    }
}

__device__ __forceinline__ unsigned getword(const unsigned* row, int start) {
    int w = start >> 5;
    int sh = start & 31;
    unsigned lo = ((unsigned)w < 8u) ? row[w] : 0u;
    unsigned hi = ((unsigned)(w + 1) < 8u) ? row[w + 1] : 0u;
    return __funnelshift_r(lo, hi, sh);
}
__device__ __forceinline__ uint4 bshl(uint4 v, int s) {
    return make_uint4(v.x << s, __funnelshift_l(v.x, v.y, s),
                      __funnelshift_l(v.y, v.z, s), __funnelshift_l(v.z, v.w, s));
}
__device__ __forceinline__ uint4 bshr(uint4 v, int s) {
    return make_uint4(__funnelshift_r(v.x, v.y, s), __funnelshift_r(v.y, v.z, s),
                      __funnelshift_r(v.z, v.w, s), v.w >> s);
}
__device__ __forceinline__ uint4 bor(uint4 a, uint4 b) {
    return make_uint4(a.x | b.x, a.y | b.y, a.z | b.z, a.w | b.w);
}
__device__ __forceinline__ unsigned hmax2u(unsigned a, unsigned b) {
    __half2 r = __hmax2(*(__half2*)&a, *(__half2*)&b);
    return *(unsigned*)&r;
}
__device__ __forceinline__ unsigned hmin2u(unsigned a, unsigned b) {
    __half2 r = __hmin2(*(__half2*)&a, *(__half2*)&b);
    return *(unsigned*)&r;
}
__device__ __forceinline__ uint4 h8max(uint4 a, uint4 b) {
    return make_uint4(hmax2u(a.x, b.x), hmax2u(a.y, b.y),
                      hmax2u(a.z, b.z), hmax2u(a.w, b.w));
}
__device__ __forceinline__ uint4 h8min(uint4 a, uint4 b) {
    return make_uint4(hmin2u(a.x, b.x), hmin2u(a.y, b.y),
                      hmin2u(a.z, b.z), hmin2u(a.w, b.w));
}

__global__ void __launch_bounds__(512, 1) k_flood(float* __restrict__ out) {
    extern __shared__ __half smh[];
    __half* A  = smh;
    __half* Bt = smh + ARRH;
    __half* M  = smh + 2 * ARRH;
    __shared__ uint4 Gs[RS];
    __shared__ uint4 Gh[RS];
    __shared__ uint4 Gm[RS];
    __shared__ float wpart[16];
    __shared__ int   s_last;

    int ch  = blockIdx.x;
    unsigned tid = threadIdx.x;
    int b   = ch >> 5;
    const float c0log = -logf(1.0f - 1e-7f);

    bool hasseed = (g_scnt[ch] != 0);
    if (!hasseed) {
        if (tid == 0) g_partial[ch] = 65536.0f * c0log;
    } else {
        int sr = g_sr[ch], sc = g_sc[ch];
        float sv = g_sv[ch];
        int gr0 = sr - 48, gc0 = sc - 48;

        // ---- init: zero A and M (pads included); Bt needs no init ----
        {
            uint4 z = make_uint4(0, 0, 0, 0);
            uint4* A8 = (uint4*)A;
            uint4* M8 = (uint4*)M;
            for (int i = tid; i < ARRH / 8; i += 512) { A8[i] = z; M8[i] = z; }
        }
        if (tid >= 415) {
            int gy2 = tid - 415;
            int gy = gr0 + gy2;
            uint4 gm = make_uint4(0, 0, 0, 0);
            if ((unsigned)gy < 256u) {
                const unsigned* row = &g_gtb[((size_t)b * 256 + gy) * 8];
                gm.x = getword(row, gc0);
                gm.y = getword(row, gc0 + 32);
                gm.z = getword(row, gc0 + 64);
                gm.w = getword(row, gc0 + 96);
            }
            gm.w &= 1u;
            Gm[gy2] = gm;
            Gs[gy2] = make_uint4(0, 0, 0, 0);
        }
        __syncthreads();
        for (unsigned idx = tid; idx < RS * RS; idx += 512) {
            unsigned y = idx / RS;                 // const-div
            unsigned x = idx - y * RS;
            int gy = gr0 + (int)y, gx = gc0 + (int)x;
            float m = 0.f;
            if ((unsigned)gy < 256u && (unsigned)gx < 256u)
                m = g_road[(b << 16) + (gy << 8) + gx];
            M[y * PH + PADC + x] = __float2half(m);
        }
        __syncthreads();
        if (tid == 0) {
            A[48 * PH + PADC + 48] = __float2half(sv);
            if (sv > 0.f) Gs[48].y |= (1u << 16);
        }
        __syncthreads();

        unsigned seedlo = *(unsigned*)&(__half2_raw){__float2half(sv).operator __half_raw().x, 0};

        for (int it = 0; it < 15; it++) {
            int R   = 3 * (it + 1);                // <= 45
            int lo  = 48 - R, hi = 48 + R;
            int rlo = lo - 3, rhi = hi + 3;        // within [0,96]
            int jlo = lo >> 3, jhi = hi >> 3;      // v-pass col groups (8 cols)
            int btlo = jlo << 3, bthi = (jhi << 3) + 7;  // Bt cols v-pass reads

            // --- horizontal 7-max (half2, 32-output units): A -> Bt ---
            {
                unsigned g = tid / 97u;            // const-div: col group 0..5 (0..3 used)
                int y = (int)(tid - g * 97u);
                int X = (int)(g << 5);
                if (g < 4 && y >= rlo && y <= rhi && X <= bthi && X + 31 >= btlo) {
                    const uint4* src = (const uint4*)(A + y * PH + X);  // cols X-8..X+39
                    uint4 t0 = src[0], t1 = src[1], t2 = src[2],
                          t3 = src[3], t4 = src[4], t5 = src[5];
                    unsigned v[24] = {t0.x, t0.y, t0.z, t0.w, t1.x, t1.y, t1.z, t1.w,
                                      t2.x, t2.y, t2.z, t2.w, t3.x, t3.y, t3.z, t3.w,
                                      t4.x, t4.y, t4.z, t4.w, t5.x, t5.y, t5.z, t5.w};
                    unsigned a2[23];
                    #pragma unroll
                    for (int j2 = 0; j2 < 23; j2++)
                        a2[j2] = hmax2u(v[j2], __funnelshift_r(v[j2], v[j2 + 1], 16));
                    unsigned q4[22];
                    #pragma unroll
                    for (int j2 = 0; j2 < 22; j2++)
                        q4[j2] = hmax2u(a2[j2], a2[j2 + 1]);
                    unsigned o[16];
                    #pragma unroll
                    for (int m2 = 0; m2 < 16; m2++)
                        o[m2] = hmax2u(__funnelshift_r(q4[m2 + 2], q4[m2 + 3], 16),
                                       q4[m2 + 4]);
                    uint4* dst = (uint4*)(Bt + y * PH + PADC + X);
                    dst[0] = make_uint4(o[0],  o[1],  o[2],  o[3]);
                    dst[1] = make_uint4(o[4],  o[5],  o[6],  o[7]);
                    dst[2] = make_uint4(o[8],  o[9],  o[10], o[11]);
                    dst[3] = make_uint4(o[12], o[13], o[14], o[15]);
                }
            }
            // --- gt bitwise horizontal dilate (tids 415..511, idle in h-pass) ---
            if (tid >= 415) {
                int gy2 = tid - 415;
                uint4 x = Gs[gy2];
                uint4 d = bor(x, bor(bshl(x, 1), bshr(x, 1)));
                d = bor(d, bor(bshl(x, 2), bshr(x, 2)));
                d = bor(d, bor(bshl(x, 3), bshr(x, 3)));
                Gh[gy2] = d;
            }
            __syncthreads();

            // --- vertical 7-max (van Herk, half2) + min(mask) + seed : Bt -> A ---
            {
                unsigned j = tid % 13u;            // const-div: col group (8 cols)
                unsigned band = tid / 13u;
                int y0 = lo + (int)band * 6;
                if ((int)j >= jlo && (int)j <= jhi && y0 <= hi) {
                    int hoff = PADC + ((int)j << 3);
                    uint4 r[12];
                    #pragma unroll
                    for (int i = 0; i < 12; i++) {
                        int ry = y0 - 3 + i;
                        ry = ry > rhi ? rhi : ry;
                        r[i] = *(const uint4*)(Bt + ry * PH + hoff);
                    }
                    uint4 S[7];
                    S[6] = r[6];
                    #pragma unroll
                    for (int i = 5; i >= 0; i--) S[i] = h8max(r[i], S[i + 1]);
                    uint4 P[5];
                    P[0] = r[7];
                    #pragma unroll
                    for (int i2 = 1; i2 < 5; i2++) P[i2] = h8max(P[i2 - 1], r[7 + i2]);
                    #pragma unroll
                    for (int k = 0; k < 6; k++) {
                        int y = y0 + k;
                        if (y > hi) break;
                        uint4 m = (k == 0) ? S[0] : h8max(S[k], P[k - 1]);
                        uint4 val = h8min(m, *(const uint4*)(M + y * PH + hoff));
                        if (y == 48 && j == 6u) val.x = hmax2u(val.x, seedlo);
                        *(uint4*)(A + y * PH + hoff) = val;
                    }
                }
            }
            // --- gt bitwise vertical dilate + AND mask + seed ---
            if (tid >= 415) {
                int y = tid - 415;
                int ym3 = y - 3 < 0 ? 0 : y - 3;
                int yp3 = y + 3 > 96 ? 96 : y + 3;
                uint4 acc = Gh[ym3];
                for (int yy = ym3 + 1; yy <= yp3; yy++) acc = bor(acc, Gh[yy]);
                acc.x &= Gm[y].x; acc.y &= Gm[y].y; acc.z &= Gm[y].z; acc.w &= Gm[y].w;
                if (y == 48 && sv > 0.f) acc.y |= (1u << 16);
                Gs[y] = acc;
            }
            __syncthreads();
        }

        // ---- fused BCE over the in-image +/-45 box (fp32 clip+log) ----
        int ylo = 3 > -gr0 ? 3 : -gr0;
        int yhi = 93 < 255 - gr0 ? 93 : 255 - gr0;
        int xlo = 3 > -gc0 ? 3 : -gc0;
        int xhi = 93 < 255 - gc0 ? 93 : 255 - gc0;
        int nrows2 = yhi - ylo + 1;
        float local = 0.f;
        for (unsigned u = tid; u < (unsigned)nrows2 * 13u; u += 512) {
            unsigned yy = u / 13u;                 // const-div
            unsigned g = u - yy * 13u;
            int y = ylo + (int)yy;
            int C = (int)(g << 3);
            if (C + 7 < xlo || C > xhi) continue;
            uint4 pv8 = *(const uint4*)(A + y * PH + PADC + C);
            uint4 gw = Gs[y];
            float2 f[4];
            f[0] = __half22float2(*(__half2*)&pv8.x);
            f[1] = __half22float2(*(__half2*)&pv8.y);
            f[2] = __half22float2(*(__half2*)&pv8.z);
            f[3] = __half22float2(*(__half2*)&pv8.w);
            const float* fv = (const float*)f;
            #pragma unroll
            for (int k = 0; k < 8; k++) {
                int x = C + k;
                if (x < xlo || x > xhi) continue;
                float p = fminf(fmaxf(fv[k], 1e-7f), 1.0f - 1e-7f);
                int ws = x >> 5;
                unsigned word = ws == 0 ? gw.x : ws == 1 ? gw.y : ws == 2 ? gw.z : gw.w;
                float t = ((word >> (x & 31)) & 1u) ? p : (1.0f - p);
                local -= __logf(t);
            }
        }

        #pragma unroll
        for (int off = 16; off; off >>= 1)
            local += __shfl_down_sync(0xffffffffu, local, off);
        if ((tid & 31) == 0) wpart[tid >> 5] = local;
        __syncthreads();
        if (tid == 0) {
            float s = 0.f;
            #pragma unroll
            for (int k = 0; k < 16; k++) s += wpart[k];
            float area = (float)((yhi - ylo + 1) * (xhi - xlo + 1));
            s += (65536.0f - area) * c0log;
            g_partial[ch] = s;
        }
    }

    // ---- last-block finalize ----
    if (tid == 0) {
        __threadfence();
        int old = atomicAdd(&g_done, 1);
        s_last = (old == NCH - 1);
    }
    __syncthreads();
    if (s_last && tid < 32) {
        float v = g_partial[tid] + g_partial[tid + 32] +
                  g_partial[tid + 64] + g_partial[tid + 96];
        #pragma unroll
        for (int off = 16; off; off >>= 1)
            v += __shfl_down_sync(0xffffffffu, v, off);
        if (tid == 0) {
            out[0] = 0.5f * v / 8388608.0f;
            g_done = 0;
        }
    }
}

extern "C" void kernel_launch(void* const* d_in, const int* in_sizes, int n_in,
                              void* d_out, int out_size) {
    const float* cls = (const float*)d_in[0];
    const int* lab   = (const int*)d_in[1];
    const float4* seeds = (const float4*)d_in[2];

    cudaFuncSetAttribute(k_flood, cudaFuncAttributeMaxDynamicSharedMemorySize, SMEM_BYTES);

    k_prep<<<2048, 256>>>(cls, lab, seeds);
    k_flood<<<128, 512, SMEM_BYTES>>>((float*)d_out);
}